// round 1
// baseline (speedup 1.0000x reference)
#include <cuda_runtime.h>
#include <math.h>

#define NM 1024
#define HH 256
#define WW 256
#define HW (HH * WW)

#define PRED_IOU_THRESH   0.88f
#define STABILITY_THRESH  0.95f
#define BOX_NMS_THRESH    0.7f

// Scratch (device globals: no allocation allowed)
__device__ float g_box[NM * 4];   // per-mask xyxy (empty -> 0)
__device__ int   g_sval[NM];      // stability >= thresh
__device__ float g_gated[NM];     // iou * keep

// ---------------------------------------------------------------------------
// Kernel 1: per-mask stats. One block per mask, 256 threads, float4 loads.
// Computes: hi = #(logit > 1), lo = #(logit > -1), bbox of (logit > 0).
// ---------------------------------------------------------------------------
__global__ __launch_bounds__(256) void stats_kernel(const float* __restrict__ logits) {
    const int n = blockIdx.x;
    const float4* __restrict__ p = (const float4*)(logits + (size_t)n * HW);
    const int t = threadIdx.x;

    int hi = 0, lo = 0;
    int minx = WW, maxx = -1, miny = HH, maxy = -1;

#pragma unroll 4
    for (int k = 0; k < 64; k++) {
        const int i4 = t + (k << 8);        // coalesced across threads
        const float4 v = p[i4];
        const int base = i4 << 2;           // flat pixel index of v.x
        hi += (v.x > 1.f) + (v.y > 1.f) + (v.z > 1.f) + (v.w > 1.f);
        lo += (v.x > -1.f) + (v.y > -1.f) + (v.z > -1.f) + (v.w > -1.f);
        const bool bx = v.x > 0.f, by = v.y > 0.f, bz = v.z > 0.f, bw = v.w > 0.f;
        if (bx || by || bz || bw) {
            const int y = base >> 8;
            const int x0 = base & 255;      // 4 pixels are same row (W=256, /4)
            miny = min(miny, y);
            maxy = max(maxy, y);
            const int lx = bx ? x0 : (by ? x0 + 1 : (bz ? x0 + 2 : x0 + 3));
            const int rx = bw ? x0 + 3 : (bz ? x0 + 2 : (by ? x0 + 1 : x0));
            minx = min(minx, lx);
            maxx = max(maxx, rx);
        }
    }

    // warp reduce
#pragma unroll
    for (int o = 16; o > 0; o >>= 1) {
        hi   += __shfl_xor_sync(0xffffffffu, hi, o);
        lo   += __shfl_xor_sync(0xffffffffu, lo, o);
        minx  = min(minx, __shfl_xor_sync(0xffffffffu, minx, o));
        maxx  = max(maxx, __shfl_xor_sync(0xffffffffu, maxx, o));
        miny  = min(miny, __shfl_xor_sync(0xffffffffu, miny, o));
        maxy  = max(maxy, __shfl_xor_sync(0xffffffffu, maxy, o));
    }

    __shared__ int s[8][6];
    const int w = t >> 5, l = t & 31;
    if (l == 0) {
        s[w][0] = hi;   s[w][1] = lo;
        s[w][2] = minx; s[w][3] = maxx;
        s[w][4] = miny; s[w][5] = maxy;
    }
    __syncthreads();
    if (t == 0) {
#pragma unroll
        for (int i = 1; i < 8; i++) {
            hi += s[i][0]; lo += s[i][1];
            minx = min(minx, s[i][2]); maxx = max(maxx, s[i][3]);
            miny = min(miny, s[i][4]); maxy = max(maxy, s[i][5]);
        }
        const float stab = (float)hi / fmaxf((float)lo, 1.0f);
        g_sval[n] = (stab >= STABILITY_THRESH) ? 1 : 0;
        float4 bx;
        if (maxx < 0) {                     // empty mask
            bx = make_float4(0.f, 0.f, 0.f, 0.f);
        } else {
            bx = make_float4((float)minx, (float)miny, (float)maxx, (float)maxy);
        }
        ((float4*)g_box)[n] = bx;
    }
}

// ---------------------------------------------------------------------------
// Kernel 2: NMS. Single block, 1024 threads (thread == mask).
// Rank-sort reproduces stable argsort of -(valid? score : -inf),
// then greedy suppression over the valid prefix only.
// ---------------------------------------------------------------------------
__device__ __forceinline__ float box_iou(const float4 a, const float4 b) {
    const float x0 = fmaxf(a.x, b.x);
    const float y0 = fmaxf(a.y, b.y);
    const float x1 = fminf(a.z, b.z);
    const float y1 = fminf(a.w, b.w);
    const float inter = fmaxf(x1 - x0, 0.f) * fmaxf(y1 - y0, 0.f);
    const float aa = fmaxf(a.z - a.x, 0.f) * fmaxf(a.w - a.y, 0.f);
    const float ab = fmaxf(b.z - b.x, 0.f) * fmaxf(b.w - b.y, 0.f);
    return inter / fmaxf(aa + ab - inter, 1e-6f);
}

__global__ __launch_bounds__(1024) void nms_kernel(const float* __restrict__ iou_preds,
                                                   float* __restrict__ out_tail,
                                                   int write_keep, int write_boxes) {
    __shared__ float  skey[NM];
    __shared__ float4 sb[NM];          // sorted boxes
    __shared__ short  sidx[NM];        // sorted -> original
    __shared__ unsigned char skeep[NM];
    __shared__ unsigned char korig[NM];
    __shared__ int    s_cnt;

    const int t = threadIdx.x;
    const float score = iou_preds[t];
    const int valid = g_sval[t] && (score > PRED_IOU_THRESH);
    const float key = valid ? score : -INFINITY;
    skey[t] = key;
    if (t == 0) s_cnt = 0;
    __syncthreads();

    // stable descending rank
    int rank = 0;
    for (int j = 0; j < NM; j++) {
        const float kj = skey[j];
        rank += (kj > key) || (kj == key && j < t);
    }
    sb[rank]    = ((const float4*)g_box)[t];
    sidx[rank]  = (short)t;
    skeep[rank] = (unsigned char)valid;
    if (valid) atomicAdd(&s_cnt, 1);
    __syncthreads();
    const int V = s_cnt;                 // valid entries occupy ranks [0, V)
    const float4 mybox = sb[t];

    for (int i = 0; i < V; i++) {
        __syncthreads();
        if (skeep[i]) {
            const float v = box_iou(sb[i], mybox);
            if (t > i && v > BOX_NMS_THRESH) skeep[t] = 0;
        }
    }
    __syncthreads();

    // back to original order
    korig[sidx[t]] = skeep[t];
    __syncthreads();
    const int kept = korig[t];
    g_gated[t] = kept ? score : 0.f;

    if (write_keep)  out_tail[t] = kept ? 1.0f : 0.0f;
    if (write_boxes) ((float4*)(out_tail + NM))[t] = ((const float4*)g_box)[t];
}

// ---------------------------------------------------------------------------
// Kernel 3: output fill. grid (1024, 16) x 256 threads; 4 float4 per thread.
// gated==0 masks write zeros WITHOUT reading logits (saves ~95% of reads).
// ---------------------------------------------------------------------------
__global__ __launch_bounds__(256) void out_kernel(const float* __restrict__ logits,
                                                  float* __restrict__ out) {
    const int n = blockIdx.x;
    const float g = g_gated[n];
    float4* __restrict__ o = (float4*)(out + (size_t)n * HW);
    const int i0 = (blockIdx.y << 10) + threadIdx.x;

    if (g == 0.f) {
        const float4 z = make_float4(0.f, 0.f, 0.f, 0.f);
#pragma unroll
        for (int k = 0; k < 4; k++) o[i0 + (k << 8)] = z;
    } else {
        const float4* __restrict__ p = (const float4*)(logits + (size_t)n * HW);
#pragma unroll
        for (int k = 0; k < 4; k++) {
            const int i = i0 + (k << 8);
            float4 v = p[i];
            v.x = g / (1.f + __expf(-v.x));
            v.y = g / (1.f + __expf(-v.y));
            v.z = g / (1.f + __expf(-v.z));
            v.w = g / (1.f + __expf(-v.w));
            o[i] = v;
        }
    }
}

extern "C" void kernel_launch(void* const* d_in, const int* in_sizes, int n_in,
                              void* d_out, int out_size) {
    const float* logits = (const float*)d_in[0];
    const float* iou    = (const float*)d_in[1];
    if (n_in >= 2 && in_sizes[0] == NM) {      // defensive: input order swap
        logits = (const float*)d_in[1];
        iou    = (const float*)d_in[0];
    }
    float* out = (float*)d_out;

    const long long tail = (long long)out_size - (long long)NM * HW;
    const int write_keep  = tail >= NM;
    const int write_boxes = tail >= 5 * NM;

    stats_kernel<<<NM, 256>>>(logits);
    nms_kernel<<<1, NM>>>(iou, out + (size_t)NM * HW, write_keep, write_boxes);
    out_kernel<<<dim3(NM, 16), 256>>>(logits, out);
}

// round 2
// speedup vs baseline: 1.0117x; 1.0117x over previous
#include <cuda_runtime.h>
#include <math.h>

#define NM 1024
#define HH 256
#define WW 256
#define HW (HH * WW)

#define PRED_IOU_THRESH   0.88f
#define STABILITY_THRESH  0.95f
#define BOX_NMS_THRESH    0.7f

// Scratch (device globals: no allocation allowed)
__device__ float g_box[NM * 4];   // per-mask xyxy (empty -> 0)
__device__ int   g_sval[NM];      // stability >= thresh
__device__ float g_gated[NM];     // iou * keep

// ---------------------------------------------------------------------------
// Kernel 1 (fused): per-mask stats + zero-fill of the output region.
// One block per mask, 256 threads, float4 loads + float4 zero stores.
// Computes: hi = #(logit > 1), lo = #(logit > -1), bbox of (logit > 0),
// while streaming zeros into out[n] (kept masks get overwritten later).
// ---------------------------------------------------------------------------
__global__ __launch_bounds__(256) void stats_zero_kernel(const float* __restrict__ logits,
                                                         float* __restrict__ out) {
    const int n = blockIdx.x;
    const float4* __restrict__ p = (const float4*)(logits + (size_t)n * HW);
    float4* __restrict__ o = (float4*)(out + (size_t)n * HW);
    const int t = threadIdx.x;

    int hi = 0, lo = 0;
    int minx = WW, maxx = -1, miny = HH, maxy = -1;
    const float4 z = make_float4(0.f, 0.f, 0.f, 0.f);

#pragma unroll 4
    for (int k = 0; k < 64; k++) {
        const int i4 = t + (k << 8);        // coalesced across threads
        const float4 v = p[i4];
        o[i4] = z;                          // fused zero-fill (independent store)
        const int base = i4 << 2;           // flat pixel index of v.x
        hi += (v.x > 1.f) + (v.y > 1.f) + (v.z > 1.f) + (v.w > 1.f);
        lo += (v.x > -1.f) + (v.y > -1.f) + (v.z > -1.f) + (v.w > -1.f);
        const bool bx = v.x > 0.f, by = v.y > 0.f, bz = v.z > 0.f, bw = v.w > 0.f;
        if (bx || by || bz || bw) {
            const int y = base >> 8;
            const int x0 = base & 255;      // 4 pixels are same row (W=256, /4)
            miny = min(miny, y);
            maxy = max(maxy, y);
            const int lx = bx ? x0 : (by ? x0 + 1 : (bz ? x0 + 2 : x0 + 3));
            const int rx = bw ? x0 + 3 : (bz ? x0 + 2 : (by ? x0 + 1 : x0));
            minx = min(minx, lx);
            maxx = max(maxx, rx);
        }
    }

    // warp reduce
#pragma unroll
    for (int oo = 16; oo > 0; oo >>= 1) {
        hi   += __shfl_xor_sync(0xffffffffu, hi, oo);
        lo   += __shfl_xor_sync(0xffffffffu, lo, oo);
        minx  = min(minx, __shfl_xor_sync(0xffffffffu, minx, oo));
        maxx  = max(maxx, __shfl_xor_sync(0xffffffffu, maxx, oo));
        miny  = min(miny, __shfl_xor_sync(0xffffffffu, miny, oo));
        maxy  = max(maxy, __shfl_xor_sync(0xffffffffu, maxy, oo));
    }

    __shared__ int s[8][6];
    const int w = t >> 5, l = t & 31;
    if (l == 0) {
        s[w][0] = hi;   s[w][1] = lo;
        s[w][2] = minx; s[w][3] = maxx;
        s[w][4] = miny; s[w][5] = maxy;
    }
    __syncthreads();
    if (t == 0) {
#pragma unroll
        for (int i = 1; i < 8; i++) {
            hi += s[i][0]; lo += s[i][1];
            minx = min(minx, s[i][2]); maxx = max(maxx, s[i][3]);
            miny = min(miny, s[i][4]); maxy = max(maxy, s[i][5]);
        }
        const float stab = (float)hi / fmaxf((float)lo, 1.0f);
        g_sval[n] = (stab >= STABILITY_THRESH) ? 1 : 0;
        float4 bx;
        if (maxx < 0) {                     // empty mask
            bx = make_float4(0.f, 0.f, 0.f, 0.f);
        } else {
            bx = make_float4((float)minx, (float)miny, (float)maxx, (float)maxy);
        }
        ((float4*)g_box)[n] = bx;
    }
}

// ---------------------------------------------------------------------------
// Kernel 2: NMS. Single block, 1024 threads (thread == mask).
// Rank-sort reproduces stable argsort of -(valid? score : -inf),
// then greedy suppression over the valid prefix only.
// ---------------------------------------------------------------------------
__device__ __forceinline__ float box_iou(const float4 a, const float4 b) {
    const float x0 = fmaxf(a.x, b.x);
    const float y0 = fmaxf(a.y, b.y);
    const float x1 = fminf(a.z, b.z);
    const float y1 = fminf(a.w, b.w);
    const float inter = fmaxf(x1 - x0, 0.f) * fmaxf(y1 - y0, 0.f);
    const float aa = fmaxf(a.z - a.x, 0.f) * fmaxf(a.w - a.y, 0.f);
    const float ab = fmaxf(b.z - b.x, 0.f) * fmaxf(b.w - b.y, 0.f);
    return inter / fmaxf(aa + ab - inter, 1e-6f);
}

__global__ __launch_bounds__(1024) void nms_kernel(const float* __restrict__ iou_preds,
                                                   float* __restrict__ out_tail,
                                                   int write_keep, int write_boxes) {
    __shared__ float  skey[NM];
    __shared__ float4 sb[NM];          // sorted boxes
    __shared__ short  sidx[NM];        // sorted -> original
    __shared__ unsigned char skeep[NM];
    __shared__ unsigned char korig[NM];
    __shared__ int    s_cnt;

    const int t = threadIdx.x;
    const float score = iou_preds[t];
    const int valid = g_sval[t] && (score > PRED_IOU_THRESH);
    const float key = valid ? score : -INFINITY;
    skey[t] = key;
    if (t == 0) s_cnt = 0;
    __syncthreads();

    // stable descending rank
    int rank = 0;
    for (int j = 0; j < NM; j++) {
        const float kj = skey[j];
        rank += (kj > key) || (kj == key && j < t);
    }
    sb[rank]    = ((const float4*)g_box)[t];
    sidx[rank]  = (short)t;
    skeep[rank] = (unsigned char)valid;
    if (valid) atomicAdd(&s_cnt, 1);
    __syncthreads();
    const int V = s_cnt;                 // valid entries occupy ranks [0, V)
    const float4 mybox = sb[t];

    for (int i = 0; i < V; i++) {
        __syncthreads();
        if (skeep[i]) {
            const float v = box_iou(sb[i], mybox);
            if (t > i && v > BOX_NMS_THRESH) skeep[t] = 0;
        }
    }
    __syncthreads();

    // back to original order
    korig[sidx[t]] = skeep[t];
    __syncthreads();
    const int kept = korig[t];
    g_gated[t] = kept ? score : 0.f;

    if (write_keep)  out_tail[t] = kept ? 1.0f : 0.0f;
    if (write_boxes) ((float4*)(out_tail + NM))[t] = ((const float4*)g_box)[t];
}

// ---------------------------------------------------------------------------
// Kernel 3: sparse output fill. grid (1024, 16) x 256 threads; only kept
// masks (g_gated != 0) do work — ~95% of blocks exit immediately since the
// zero-fill already happened in kernel 1.
// ---------------------------------------------------------------------------
__global__ __launch_bounds__(256) void out_kernel(const float* __restrict__ logits,
                                                  float* __restrict__ out) {
    const int n = blockIdx.x;
    const float g = g_gated[n];
    if (g == 0.f) return;

    float4* __restrict__ o = (float4*)(out + (size_t)n * HW);
    const float4* __restrict__ p = (const float4*)(logits + (size_t)n * HW);
    const int i0 = (blockIdx.y << 10) + threadIdx.x;

#pragma unroll
    for (int k = 0; k < 4; k++) {
        const int i = i0 + (k << 8);
        float4 v = p[i];
        v.x = g / (1.f + __expf(-v.x));
        v.y = g / (1.f + __expf(-v.y));
        v.z = g / (1.f + __expf(-v.z));
        v.w = g / (1.f + __expf(-v.w));
        o[i] = v;
    }
}

extern "C" void kernel_launch(void* const* d_in, const int* in_sizes, int n_in,
                              void* d_out, int out_size) {
    const float* logits = (const float*)d_in[0];
    const float* iou    = (const float*)d_in[1];
    if (n_in >= 2 && in_sizes[0] == NM) {      // defensive: input order swap
        logits = (const float*)d_in[1];
        iou    = (const float*)d_in[0];
    }
    float* out = (float*)d_out;

    const long long tail = (long long)out_size - (long long)NM * HW;
    const int write_keep  = tail >= NM;
    const int write_boxes = tail >= 5 * NM;

    stats_zero_kernel<<<NM, 256>>>(logits, out);
    nms_kernel<<<1, NM>>>(iou, out + (size_t)NM * HW, write_keep, write_boxes);
    out_kernel<<<dim3(NM, 16), 256>>>(logits, out);
}

// round 3
// speedup vs baseline: 1.2547x; 1.2401x over previous
#include <cuda_runtime.h>
#include <math.h>

#define NM 1024
#define HH 256
#define WW 256
#define HW (HH * WW)

#define PRED_IOU_THRESH   0.88f
#define STABILITY_THRESH  0.95f
#define BOX_NMS_THRESH    0.7f

// Scratch (device globals: no allocation allowed)
__device__ float g_box[NM * 4];   // per-mask xyxy (empty -> 0)
__device__ int   g_sval[NM];      // stability >= thresh
__device__ float g_gated[NM];     // iou * keep

// ---------------------------------------------------------------------------
// Kernel 1 (fused): per-mask stats + zero-fill of the output region.
// One block per mask, 256 threads, streaming float4 loads + zero stores.
// ---------------------------------------------------------------------------
__global__ __launch_bounds__(256) void stats_zero_kernel(const float* __restrict__ logits,
                                                         float* __restrict__ out) {
    const int n = blockIdx.x;
    const float4* __restrict__ p = (const float4*)(logits + (size_t)n * HW);
    float4* __restrict__ o = (float4*)(out + (size_t)n * HW);
    const int t = threadIdx.x;

    int hi = 0, lo = 0;
    int minx = WW, maxx = -1, miny = HH, maxy = -1;
    const float4 z = make_float4(0.f, 0.f, 0.f, 0.f);

#pragma unroll 8
    for (int k = 0; k < 64; k++) {
        const int i4 = t + (k << 8);        // coalesced across threads
        const float4 v = __ldcs(&p[i4]);    // streaming read (no reuse)
        __stcs(&o[i4], z);                  // streaming zero-fill
        const int base = i4 << 2;           // flat pixel index of v.x
        hi += (v.x > 1.f) + (v.y > 1.f) + (v.z > 1.f) + (v.w > 1.f);
        lo += (v.x > -1.f) + (v.y > -1.f) + (v.z > -1.f) + (v.w > -1.f);
        const bool bx = v.x > 0.f, by = v.y > 0.f, bz = v.z > 0.f, bw = v.w > 0.f;
        if (bx || by || bz || bw) {
            const int y = base >> 8;
            const int x0 = base & 255;      // 4 pixels same row (W=256, /4)
            miny = min(miny, y);
            maxy = max(maxy, y);
            const int lx = bx ? x0 : (by ? x0 + 1 : (bz ? x0 + 2 : x0 + 3));
            const int rx = bw ? x0 + 3 : (bz ? x0 + 2 : (by ? x0 + 1 : x0));
            minx = min(minx, lx);
            maxx = max(maxx, rx);
        }
    }

    // warp reduce
#pragma unroll
    for (int oo = 16; oo > 0; oo >>= 1) {
        hi   += __shfl_xor_sync(0xffffffffu, hi, oo);
        lo   += __shfl_xor_sync(0xffffffffu, lo, oo);
        minx  = min(minx, __shfl_xor_sync(0xffffffffu, minx, oo));
        maxx  = max(maxx, __shfl_xor_sync(0xffffffffu, maxx, oo));
        miny  = min(miny, __shfl_xor_sync(0xffffffffu, miny, oo));
        maxy  = max(maxy, __shfl_xor_sync(0xffffffffu, maxy, oo));
    }

    __shared__ int s[8][6];
    const int w = t >> 5, l = t & 31;
    if (l == 0) {
        s[w][0] = hi;   s[w][1] = lo;
        s[w][2] = minx; s[w][3] = maxx;
        s[w][4] = miny; s[w][5] = maxy;
    }
    __syncthreads();
    if (t == 0) {
#pragma unroll
        for (int i = 1; i < 8; i++) {
            hi += s[i][0]; lo += s[i][1];
            minx = min(minx, s[i][2]); maxx = max(maxx, s[i][3]);
            miny = min(miny, s[i][4]); maxy = max(maxy, s[i][5]);
        }
        const float stab = (float)hi / fmaxf((float)lo, 1.0f);
        g_sval[n] = (stab >= STABILITY_THRESH) ? 1 : 0;
        float4 bx;
        if (maxx < 0) {                     // empty mask
            bx = make_float4(0.f, 0.f, 0.f, 0.f);
        } else {
            bx = make_float4((float)minx, (float)miny, (float)maxx, (float)maxy);
        }
        ((float4*)g_box)[n] = bx;
    }
}

// ---------------------------------------------------------------------------
// Kernel 2: compact NMS. Single block, 1024 threads.
// Only valid entries (V << 1024) participate in the sort + suppression:
// invalid entries have key=-inf, keep0=false, and never suppress anyone,
// so their final keep is false regardless — no need to rank them.
// Stable order = score desc, original index asc (matches jnp.argsort).
// ---------------------------------------------------------------------------
__device__ __forceinline__ float box_iou(const float4 a, const float4 b) {
    const float x0 = fmaxf(a.x, b.x);
    const float y0 = fmaxf(a.y, b.y);
    const float x1 = fminf(a.z, b.z);
    const float y1 = fminf(a.w, b.w);
    const float inter = fmaxf(x1 - x0, 0.f) * fmaxf(y1 - y0, 0.f);
    const float aa = fmaxf(a.z - a.x, 0.f) * fmaxf(a.w - a.y, 0.f);
    const float ab = fmaxf(b.z - b.x, 0.f) * fmaxf(b.w - b.y, 0.f);
    return inter / fmaxf(aa + ab - inter, 1e-6f);
}

__global__ __launch_bounds__(1024) void nms_kernel(const float* __restrict__ iou_preds,
                                                   float* __restrict__ out_tail,
                                                   int write_keep, int write_boxes) {
    __shared__ float  cscore[NM];   // compacted scores (unordered)
    __shared__ short  cidx[NM];     // compacted original indices
    __shared__ float4 cbox[NM];
    __shared__ float4 rb[NM];       // rank-ordered boxes
    __shared__ short  ridx[NM];
    __shared__ unsigned char rkeep[NM];
    __shared__ unsigned char korig[NM];
    __shared__ int    s_cnt;

    const int t = threadIdx.x;
    const float score = iou_preds[t];
    const int valid = g_sval[t] && (score > PRED_IOU_THRESH);
    korig[t] = 0;
    if (t == 0) s_cnt = 0;
    __syncthreads();

    int slot = -1;
    if (valid) {
        slot = atomicAdd(&s_cnt, 1);
        cscore[slot] = score;
        cidx[slot]   = (short)t;
        cbox[slot]   = ((const float4*)g_box)[t];
    }
    __syncthreads();
    const int V = s_cnt;

    // stable descending rank among valid entries only (V^2 work, V threads)
    if (slot >= 0) {
        const float s0 = cscore[slot];
        const short i0 = cidx[slot];
        int rank = 0;
        for (int j = 0; j < V; j++) {
            const float sj = cscore[j];
            rank += (sj > s0) || (sj == s0 && cidx[j] < i0);
        }
        rb[rank]    = cbox[slot];
        ridx[rank]  = i0;
        rkeep[rank] = 1;
    }
    __syncthreads();

    float4 mybox = make_float4(0.f, 0.f, 0.f, 0.f);
    if (t < V) mybox = rb[t];

    for (int i = 0; i < V; i++) {
        if (t < V && t > i && rkeep[i]) {
            if (box_iou(rb[i], mybox) > BOX_NMS_THRESH) rkeep[t] = 0;
        }
        __syncthreads();
    }

    if (t < V && rkeep[t]) korig[ridx[t]] = 1;
    __syncthreads();

    const int kept = korig[t];
    g_gated[t] = kept ? score : 0.f;

    if (write_keep)  out_tail[t] = kept ? 1.0f : 0.0f;
    if (write_boxes) ((float4*)(out_tail + NM))[t] = ((const float4*)g_box)[t];
}

// ---------------------------------------------------------------------------
// Kernel 3: sparse output fill — only kept masks do work; the zero-fill
// already happened in kernel 1.
// ---------------------------------------------------------------------------
__global__ __launch_bounds__(256) void out_kernel(const float* __restrict__ logits,
                                                  float* __restrict__ out) {
    const int n = blockIdx.x;
    const float g = g_gated[n];
    if (g == 0.f) return;

    float4* __restrict__ o = (float4*)(out + (size_t)n * HW);
    const float4* __restrict__ p = (const float4*)(logits + (size_t)n * HW);
    const int i0 = (blockIdx.y << 10) + threadIdx.x;

#pragma unroll
    for (int k = 0; k < 4; k++) {
        const int i = i0 + (k << 8);
        float4 v = __ldcs(&p[i]);
        v.x = g / (1.f + __expf(-v.x));
        v.y = g / (1.f + __expf(-v.y));
        v.z = g / (1.f + __expf(-v.z));
        v.w = g / (1.f + __expf(-v.w));
        __stcs(&o[i], v);
    }
}

extern "C" void kernel_launch(void* const* d_in, const int* in_sizes, int n_in,
                              void* d_out, int out_size) {
    const float* logits = (const float*)d_in[0];
    const float* iou    = (const float*)d_in[1];
    if (n_in >= 2 && in_sizes[0] == NM) {      // defensive: input order swap
        logits = (const float*)d_in[1];
        iou    = (const float*)d_in[0];
    }
    float* out = (float*)d_out;

    const long long tail = (long long)out_size - (long long)NM * HW;
    const int write_keep  = tail >= NM;
    const int write_boxes = tail >= 5 * NM;

    stats_zero_kernel<<<NM, 256>>>(logits, out);
    nms_kernel<<<1, NM>>>(iou, out + (size_t)NM * HW, write_keep, write_boxes);
    out_kernel<<<dim3(NM, 16), 256>>>(logits, out);
}